// round 1
// baseline (speedup 1.0000x reference)
#include <cuda_runtime.h>
#include <cstdint>

// ---------------- problem dims ----------------
#define Bb 32
#define Nn 1024
#define Cc 1024
#define Ll 16
#define Hh 512
#define BNC (Bb*Nn*Cc)       // 33554432
#define BLC (Bb*Ll*Cc)       // 524288

// ---------------- scratch (static device allocations are allowed) ----------------
__device__ float g_attn[Bb*Ll*Nn];   // tokenizer logits -> softmax weights, [b][l][n]
__device__ float g_T[BLC];           // tokens [b][l][c]
__device__ float g_Tp[4*BLC];        // partial sums for T (4 n-chunks, deterministic)
__device__ float g_k[Bb*Ll*Hh];
__device__ float g_q[Bb*Ll*Hh];
__device__ float g_Td[BLC];          // T_dash
__device__ float g_h[BLC];           // relu(f1) hidden
__device__ float g_TK[BLC];          // T_out @ k_W + k_b
__device__ float g_U[BLC];           // TK @ q_W^T
__device__ float g_cb[Bb*Ll];        // q_b . TK[b,l]

// =================================================================
// K1: proj[b][l][n] = sum_c X[b,n,c]*tok_W[c,l] + tok_b[l]
// stored TRANSPOSED as [b][l][n] so softmax-over-n is row-contiguous.
// grid 256 blocks x 128 threads; block = 128 pixel rows, all 16 l.
// thread tile: 4 pixels x 4 l.
// =================================================================
__global__ __launch_bounds__(128) void k1_proj(
    const float* __restrict__ X, const float* __restrict__ W,
    const float* __restrict__ bias, float* __restrict__ out)
{
    __shared__ float Xs[32][132];   // [k][p], stride 132 floats (16B aligned)
    __shared__ float Ws[32][16];
    __shared__ float bs[16];

    int tid = threadIdx.x;
    int r0  = blockIdx.x * 128;          // global pixel row (b*N + n)
    int b   = r0 >> 10;
    int n0  = r0 & 1023;
    int lg  = tid & 3;                   // l group (4 l's)
    int pg  = tid >> 2;                  // pixel group (4 pixels)

    if (tid < 16) bs[tid] = bias[tid];

    float acc[4][4];
#pragma unroll
    for (int i = 0; i < 4; i++)
#pragma unroll
        for (int j = 0; j < 4; j++) acc[i][j] = 0.f;

    for (int k0 = 0; k0 < Cc; k0 += 32) {
        __syncthreads();
        // load X tile 128 pixels x 32 k (transposed into smem)
#pragma unroll
        for (int j = 0; j < 8; j++) {
            int v = tid + 128*j;
            int p = v >> 3, kq = v & 7;
            float4 f = *(const float4*)(X + (size_t)(r0 + p)*Cc + k0 + kq*4);
            Xs[kq*4+0][p] = f.x; Xs[kq*4+1][p] = f.y;
            Xs[kq*4+2][p] = f.z; Xs[kq*4+3][p] = f.w;
        }
        // load W tile 32 x 16
        {
            int c = tid >> 2, lq = tid & 3;
            float4 wf = *(const float4*)(W + (size_t)(k0 + c)*Ll + lq*4);
            *(float4*)&Ws[c][lq*4] = wf;
        }
        __syncthreads();
#pragma unroll 8
        for (int kk = 0; kk < 32; kk++) {
            float4 xv = *(float4*)&Xs[kk][pg*4];
            float4 wv = *(float4*)&Ws[kk][lg*4];
            float xr[4] = {xv.x, xv.y, xv.z, xv.w};
            float wr[4] = {wv.x, wv.y, wv.z, wv.w};
#pragma unroll
            for (int i = 0; i < 4; i++)
#pragma unroll
                for (int j = 0; j < 4; j++)
                    acc[i][j] += xr[i]*wr[j];
        }
    }
#pragma unroll
    for (int i = 0; i < 4; i++) {
        int n = n0 + pg*4 + i;
#pragma unroll
        for (int j = 0; j < 4; j++) {
            int l = lg*4 + j;
            out[((b*Ll + l) << 10) + n] = acc[i][j] + bs[l];
        }
    }
}

// =================================================================
// K2: softmax over n (1024) for each row [b][l]. in-place on g_attn.
// grid 512 x 256 threads, float4 per thread.
// =================================================================
__global__ __launch_bounds__(256) void k2_softmax(float* __restrict__ a)
{
    __shared__ float red[256];
    int row = blockIdx.x, tid = threadIdx.x;
    float4* p = (float4*)(a + ((size_t)row << 10));
    float4 v = p[tid];

    float m = fmaxf(fmaxf(v.x, v.y), fmaxf(v.z, v.w));
    red[tid] = m; __syncthreads();
    for (int s = 128; s > 0; s >>= 1) {
        if (tid < s) red[tid] = fmaxf(red[tid], red[tid+s]);
        __syncthreads();
    }
    float mx = red[0]; __syncthreads();

    v.x = __expf(v.x - mx); v.y = __expf(v.y - mx);
    v.z = __expf(v.z - mx); v.w = __expf(v.w - mx);
    red[tid] = v.x + v.y + v.z + v.w; __syncthreads();
    for (int s = 128; s > 0; s >>= 1) {
        if (tid < s) red[tid] += red[tid+s];
        __syncthreads();
    }
    float inv = 1.0f / red[0];
    v.x *= inv; v.y *= inv; v.z *= inv; v.w *= inv;
    p[tid] = v;
}

// =================================================================
// K3: partial T: Tp[ny][b][l][c] = sum_{n in chunk ny} attn[b][l][n]*X[b][n][c]
// grid (2 c-chunks, 4 n-chunks, 32 b) x 128 threads; thread owns 4 c.
// =================================================================
__global__ __launch_bounds__(128) void k3_aggregate(
    const float* __restrict__ X, const float* __restrict__ attn,
    float* __restrict__ Tp)
{
    __shared__ float As[256][16];    // [nn][l]
    int tid = threadIdx.x;
    int cx = blockIdx.x, ny = blockIdx.y, b = blockIdx.z;
    int n0 = ny * 256;

#pragma unroll
    for (int s = 0; s < 32; s++) {
        int v = tid + 128*s;
        int l = v >> 8, nn = v & 255;
        As[nn][l] = attn[((b*Ll + l) << 10) + n0 + nn];
    }
    __syncthreads();

    int c4 = cx*512 + tid*4;
    float4 acc[16];
#pragma unroll
    for (int l = 0; l < 16; l++) acc[l] = make_float4(0.f,0.f,0.f,0.f);

    const float* Xb = X + (size_t)(b*Nn + n0)*Cc + c4;
#pragma unroll 4
    for (int nn = 0; nn < 256; nn++) {
        float4 xv = *(const float4*)(Xb + (size_t)nn*Cc);
#pragma unroll
        for (int lq = 0; lq < 4; lq++) {
            float4 av = *(float4*)&As[nn][lq*4];
            float ar[4] = {av.x, av.y, av.z, av.w};
#pragma unroll
            for (int i = 0; i < 4; i++) {
                float a = ar[i];
                acc[lq*4+i].x += a*xv.x; acc[lq*4+i].y += a*xv.y;
                acc[lq*4+i].z += a*xv.z; acc[lq*4+i].w += a*xv.w;
            }
        }
    }
#pragma unroll
    for (int l = 0; l < 16; l++)
        *(float4*)(Tp + (size_t)ny*BLC + ((b*Ll + l) << 10) + c4) = acc[l];
}

// K3b: T = sum of 4 partials. grid 512 x 256, one float4 each.
__global__ __launch_bounds__(256) void k3b_reduce(const float* __restrict__ Tp,
                                                  float* __restrict__ T)
{
    int idx = blockIdx.x*256 + threadIdx.x;   // float4 index, total 131072
    const float4* p = (const float4*)Tp;
    float4 a = p[idx], b = p[idx + 131072], c = p[idx + 2*131072], d = p[idx + 3*131072];
    float4 o; o.x = a.x+b.x+c.x+d.x; o.y = a.y+b.y+c.y+d.y;
    o.z = a.z+b.z+c.z+d.z; o.w = a.w+b.w+c.w+d.w;
    ((float4*)T)[idx] = o;
}

// =================================================================
// Generic fp32 GEMM: C[m][n] = sum_k A[m][k]*B[k][n] (+bias[n]) (relu) (+Res[m][n])
// transB: B given as Bt[n][k].
// Tiles: BM=32, BN=64, BK=16; 64 threads; thread tile 4x8.
// =================================================================
__global__ __launch_bounds__(64) void gemm_k(
    const float* __restrict__ A, const float* __restrict__ Bm,
    const float* __restrict__ bias, const float* __restrict__ Res,
    float* __restrict__ Cout, int M, int N, int K, int transB, int doRelu)
{
    __shared__ float As[16][36];
    __shared__ float Bs[16][68];
    int tid = threadIdx.x;
    int n0 = blockIdx.x * 64, m0 = blockIdx.y * 32;
    int tm = tid & 7, tn = tid >> 3;

    float acc[4][8];
#pragma unroll
    for (int i = 0; i < 4; i++)
#pragma unroll
        for (int j = 0; j < 8; j++) acc[i][j] = 0.f;

    for (int k0 = 0; k0 < K; k0 += 16) {
        __syncthreads();
        // A: 32 x 16, transposed into As[k][m]
#pragma unroll
        for (int j = 0; j < 2; j++) {
            int v = tid + 64*j;
            int m = v >> 2, kq = v & 3;
            float4 f = *(const float4*)(A + (size_t)(m0 + m)*K + k0 + kq*4);
            As[kq*4+0][m] = f.x; As[kq*4+1][m] = f.y;
            As[kq*4+2][m] = f.z; As[kq*4+3][m] = f.w;
        }
        if (!transB) {
#pragma unroll
            for (int j = 0; j < 4; j++) {
                int v = tid + 64*j;
                int k = v >> 4, nq = v & 15;
                float4 f = *(const float4*)(Bm + (size_t)(k0 + k)*N + n0 + nq*4);
                *(float4*)&Bs[k][nq*4] = f;
            }
        } else {
#pragma unroll
            for (int j = 0; j < 4; j++) {
                int v = tid + 64*j;
                int n = v >> 2, kq = v & 3;
                float4 f = *(const float4*)(Bm + (size_t)(n0 + n)*K + k0 + kq*4);
                Bs[kq*4+0][n] = f.x; Bs[kq*4+1][n] = f.y;
                Bs[kq*4+2][n] = f.z; Bs[kq*4+3][n] = f.w;
            }
        }
        __syncthreads();
#pragma unroll 8
        for (int kk = 0; kk < 16; kk++) {
            float4 a4 = *(float4*)&As[kk][tm*4];
            float4 b0 = *(float4*)&Bs[kk][tn*8];
            float4 b1 = *(float4*)&Bs[kk][tn*8 + 4];
            float ar[4] = {a4.x, a4.y, a4.z, a4.w};
            float br[8] = {b0.x, b0.y, b0.z, b0.w, b1.x, b1.y, b1.z, b1.w};
#pragma unroll
            for (int i = 0; i < 4; i++)
#pragma unroll
                for (int j = 0; j < 8; j++)
                    acc[i][j] += ar[i]*br[j];
        }
    }

    float bv[8];
#pragma unroll
    for (int j = 0; j < 8; j++) bv[j] = bias ? bias[n0 + tn*8 + j] : 0.f;
#pragma unroll
    for (int i = 0; i < 4; i++) {
        int m = m0 + tm*4 + i;
        float o[8];
#pragma unroll
        for (int j = 0; j < 8; j++) {
            float v = acc[i][j] + bv[j];
            if (doRelu) v = fmaxf(v, 0.f);
            o[j] = v;
        }
        if (Res) {
            const float* rp = Res + (size_t)m*N + n0 + tn*8;
            float4 r0 = *(const float4*)rp;
            float4 r1 = *(const float4*)(rp + 4);
            o[0]+=r0.x; o[1]+=r0.y; o[2]+=r0.z; o[3]+=r0.w;
            o[4]+=r1.x; o[5]+=r1.y; o[6]+=r1.z; o[7]+=r1.w;
        }
        float* cp = Cout + (size_t)m*N + n0 + tn*8;
        *(float4*)cp       = make_float4(o[0], o[1], o[2], o[3]);
        *(float4*)(cp + 4) = make_float4(o[4], o[5], o[6], o[7]);
    }
}

// =================================================================
// K5: per-batch token self-attention.
// scores[i][j] = k[b,i,:].q[b,j,:]; softmax over j; Td = T + attn @ T
// grid 32 x 256 threads.
// =================================================================
__global__ __launch_bounds__(256) void k5_attn(
    const float* __restrict__ km, const float* __restrict__ qm,
    const float* __restrict__ T, float* __restrict__ Td)
{
    __shared__ float sc[16][16];
    __shared__ float aw[16][16];
    int b = blockIdx.x, tid = threadIdx.x;
    int i = tid >> 4, j = tid & 15;

    const float4* kr = (const float4*)(km + ((size_t)b*Ll + i)*Hh);
    const float4* qr = (const float4*)(qm + ((size_t)b*Ll + j)*Hh);
    float s = 0.f;
#pragma unroll 8
    for (int t = 0; t < 128; t++) {
        float4 kv = kr[t], qv = qr[t];
        s += kv.x*qv.x + kv.y*qv.y + kv.z*qv.z + kv.w*qv.w;
    }
    sc[i][j] = s;
    __syncthreads();

    if (tid < 16) {
        float m = -1e30f;
#pragma unroll
        for (int jj = 0; jj < 16; jj++) m = fmaxf(m, sc[tid][jj]);
        float sum = 0.f;
        float e[16];
#pragma unroll
        for (int jj = 0; jj < 16; jj++) { e[jj] = __expf(sc[tid][jj] - m); sum += e[jj]; }
        float inv = 1.f/sum;
#pragma unroll
        for (int jj = 0; jj < 16; jj++) aw[tid][jj] = e[jj]*inv;
    }
    __syncthreads();

    const float4* Tb = (const float4*)(T + (size_t)b*Ll*Cc);
    float4* Tdb = (float4*)(Td + (size_t)b*Ll*Cc);
#pragma unroll
    for (int t = 0; t < 16; t++) {
        int v = tid + 256*t;
        int ii = v >> 8, c4 = v & 255;
        float4 o = Tb[(ii << 8) + c4];
#pragma unroll
        for (int jj = 0; jj < 16; jj++) {
            float a = aw[ii][jj];
            float4 tv = Tb[(jj << 8) + c4];
            o.x += a*tv.x; o.y += a*tv.y; o.z += a*tv.z; o.w += a*tv.w;
        }
        Tdb[(ii << 8) + c4] = o;
    }
}

// =================================================================
// K9b: cb[r] = q_b . TK[r,:]   (512 rows, warp per row)
// grid 64 x 256 (8 warps)
// =================================================================
__global__ __launch_bounds__(256) void k9b_cb(
    const float* __restrict__ TK, const float* __restrict__ qb,
    float* __restrict__ cb)
{
    int w = threadIdx.x >> 5, lane = threadIdx.x & 31;
    int row = blockIdx.x*8 + w;
    const float4* r4 = (const float4*)(TK + ((size_t)row << 10));
    const float4* b4 = (const float4*)qb;
    float s = 0.f;
#pragma unroll
    for (int j = 0; j < 8; j++) {
        int idx = lane + 32*j;
        float4 a = r4[idx], bb = b4[idx];
        s += a.x*bb.x + a.y*bb.y + a.z*bb.z + a.w*bb.w;
    }
#pragma unroll
    for (int off = 16; off > 0; off >>= 1)
        s += __shfl_xor_sync(0xFFFFFFFFu, s, off);
    if (lane == 0) cb[row] = s;
}

// =================================================================
// K10: projector pixel pass.
// sim[l] = X[b,n,:].U[b,l,:] + cb[b,l]; softmax over 16; X_out = X + attn@T_out
// grid 512 (16 blocks/batch, 64 pixels each) x 256 threads (8 warps x 4 pixels).
// smem: U[b] (64KB) + T_out[b] (64KB) + cb (64B), dynamic.
// =================================================================
__global__ __launch_bounds__(256) void k10_pixels(
    const float* __restrict__ X, const float* __restrict__ U,
    const float* __restrict__ Tout, const float* __restrict__ cb,
    float* __restrict__ Xout)
{
    extern __shared__ float sm[];
    float* Us = sm;             // 16*1024
    float* Ts = sm + 16384;     // 16*1024
    float* cbs = sm + 32768;    // 16

    int b  = blockIdx.x >> 4;
    int pb = blockIdx.x & 15;
    int tid = threadIdx.x;

    {
        const float4* u4 = (const float4*)(U + (size_t)b*16384);
        const float4* t4 = (const float4*)(Tout + (size_t)b*16384);
        float4* us4 = (float4*)Us; float4* ts4 = (float4*)Ts;
#pragma unroll
        for (int j = 0; j < 16; j++) {
            int idx = tid + 256*j;
            us4[idx] = u4[idx];
            ts4[idx] = t4[idx];
        }
        if (tid < 16) cbs[tid] = cb[b*Ll + tid];
    }
    __syncthreads();

    int w = tid >> 5, lane = tid & 31;
    for (int it = 0; it < 2; it++) {
        int p0 = pb*64 + it*32 + w*4;
        const float4* Xp = (const float4*)(X + (size_t)(b*Nn + p0)*Cc);
        float acc[4][16];
#pragma unroll
        for (int p = 0; p < 4; p++)
#pragma unroll
            for (int l = 0; l < 16; l++) acc[p][l] = 0.f;

#pragma unroll
        for (int j = 0; j < 8; j++) {
            int c4 = lane + 32*j;
            float4 xv[4];
#pragma unroll
            for (int p = 0; p < 4; p++) xv[p] = Xp[(p << 8) + c4];
#pragma unroll
            for (int l = 0; l < 16; l++) {
                float4 uv = ((float4*)(Us + (l << 10)))[c4];
#pragma unroll
                for (int p = 0; p < 4; p++)
                    acc[p][l] += xv[p].x*uv.x + xv[p].y*uv.y + xv[p].z*uv.z + xv[p].w*uv.w;
            }
        }
        // warp all-reduce (every lane ends with the full sums)
#pragma unroll
        for (int off = 16; off > 0; off >>= 1)
#pragma unroll
            for (int p = 0; p < 4; p++)
#pragma unroll
                for (int l = 0; l < 16; l++)
                    acc[p][l] += __shfl_xor_sync(0xFFFFFFFFu, acc[p][l], off);

        // softmax over 16 (in place, every lane computes identically)
#pragma unroll
        for (int p = 0; p < 4; p++) {
            float m = -1e30f;
#pragma unroll
            for (int l = 0; l < 16; l++) {
                acc[p][l] += cbs[l];
                m = fmaxf(m, acc[p][l]);
            }
            float s = 0.f;
#pragma unroll
            for (int l = 0; l < 16; l++) { acc[p][l] = __expf(acc[p][l] - m); s += acc[p][l]; }
            float inv = 1.f/s;
#pragma unroll
            for (int l = 0; l < 16; l++) acc[p][l] *= inv;
        }

        float4* Op = (float4*)(Xout + (size_t)(b*Nn + p0)*Cc);
#pragma unroll
        for (int j = 0; j < 8; j++) {
            int c4 = lane + 32*j;
            float4 o[4];
#pragma unroll
            for (int p = 0; p < 4; p++) o[p] = Xp[(p << 8) + c4];
#pragma unroll
            for (int l = 0; l < 16; l++) {
                float4 tv = ((float4*)(Ts + (l << 10)))[c4];
#pragma unroll
                for (int p = 0; p < 4; p++) {
                    float a = acc[p][l];
                    o[p].x += a*tv.x; o[p].y += a*tv.y;
                    o[p].z += a*tv.z; o[p].w += a*tv.w;
                }
            }
#pragma unroll
            for (int p = 0; p < 4; p++) Op[(p << 8) + c4] = o[p];
        }
    }
}

// =================================================================
extern "C" void kernel_launch(void* const* d_in, const int* in_sizes, int n_in,
                              void* d_out, int out_size)
{
    const float* X       = (const float*)d_in[0];
    // d_in[1] = T_in (unused by reference)
    const float* tok_W   = (const float*)d_in[2];
    const float* tok_b   = (const float*)d_in[3];
    const float* key_W   = (const float*)d_in[4];
    const float* key_b   = (const float*)d_in[5];
    const float* query_W = (const float*)d_in[6];
    const float* query_b = (const float*)d_in[7];
    const float* f1_W    = (const float*)d_in[8];
    const float* f1_b    = (const float*)d_in[9];
    const float* f2_W    = (const float*)d_in[10];
    const float* f2_b    = (const float*)d_in[11];
    const float* q_W     = (const float*)d_in[12];
    const float* q_b     = (const float*)d_in[13];
    const float* k_W     = (const float*)d_in[14];
    const float* k_b     = (const float*)d_in[15];

    float* Xout = (float*)d_out;
    float* Tout = (float*)d_out + (size_t)BNC;   // (X_out, T_out) concatenated

    float *p_attn, *p_T, *p_Tp, *p_k, *p_q, *p_Td, *p_h, *p_TK, *p_U, *p_cb;
    cudaGetSymbolAddress((void**)&p_attn, g_attn);
    cudaGetSymbolAddress((void**)&p_T,    g_T);
    cudaGetSymbolAddress((void**)&p_Tp,   g_Tp);
    cudaGetSymbolAddress((void**)&p_k,    g_k);
    cudaGetSymbolAddress((void**)&p_q,    g_q);
    cudaGetSymbolAddress((void**)&p_Td,   g_Td);
    cudaGetSymbolAddress((void**)&p_h,    g_h);
    cudaGetSymbolAddress((void**)&p_TK,   g_TK);
    cudaGetSymbolAddress((void**)&p_U,    g_U);
    cudaGetSymbolAddress((void**)&p_cb,   g_cb);

    cudaFuncSetAttribute(k10_pixels,
        cudaFuncAttributeMaxDynamicSharedMemorySize, (32768 + 16) * 4);

    // Phase A: tokenizer
    k1_proj<<<256, 128>>>(X, tok_W, tok_b, p_attn);
    k2_softmax<<<512, 256>>>(p_attn);
    k3_aggregate<<<dim3(2, 4, 32), 128>>>(X, p_attn, p_Tp);
    k3b_reduce<<<512, 256>>>(p_Tp, p_T);

    // Phase B: token transformer
    gemm_k<<<dim3(Hh/64, 512/32), 64>>>(p_T, key_W,   key_b,   nullptr, p_k,  512, Hh, Cc, 0, 0);
    gemm_k<<<dim3(Hh/64, 512/32), 64>>>(p_T, query_W, query_b, nullptr, p_q,  512, Hh, Cc, 0, 0);
    k5_attn<<<32, 256>>>(p_k, p_q, p_T, p_Td);
    gemm_k<<<dim3(Cc/64, 512/32), 64>>>(p_Td, f1_W, f1_b, nullptr, p_h,  512, Cc, Cc, 0, 1);
    gemm_k<<<dim3(Cc/64, 512/32), 64>>>(p_h,  f2_W, f2_b, p_Td,    Tout, 512, Cc, Cc, 0, 0);

    // Projector token-side transforms (algebraic reduction of X@q_W)
    gemm_k<<<dim3(Cc/64, 512/32), 64>>>(Tout, k_W, k_b,     nullptr, p_TK, 512, Cc, Cc, 0, 0);
    gemm_k<<<dim3(Cc/64, 512/32), 64>>>(p_TK, q_W, nullptr, nullptr, p_U,  512, Cc, Cc, 1, 0);
    k9b_cb<<<64, 256>>>(p_TK, q_b, p_cb);

    // Phase C: pixel pass
    k10_pixels<<<512, 256, (32768 + 16) * 4>>>(X, p_U, Tout, p_cb, Xout);

    (void)in_sizes; (void)n_in; (void)out_size;
}

// round 6
// speedup vs baseline: 1.7151x; 1.7151x over previous
#include <cuda_runtime.h>
#include <cstdint>

// ---------------- problem dims ----------------
#define Bb 32
#define Nn 1024
#define Cc 1024
#define Ll 16
#define Hh 512
#define BNC (Bb*Nn*Cc)       // 33554432
#define BLC (Bb*Ll*Cc)       // 524288
#define MN  (512*1024)       // chain GEMM output size

// ---------------- packed f32x2 FMA (sm_103a FFMA2, PTX-only) ----------------
union F2U { float2 f; unsigned long long u; };
__device__ __forceinline__ float2 ffma2(float2 a, float2 b, float2 c)
{
    F2U ua, ub, uc, ud;
    ua.f = a; ub.f = b; uc.f = c;
    asm("fma.rn.f32x2 %0, %1, %2, %3;"
        : "=l"(ud.u) : "l"(ua.u), "l"(ub.u), "l"(uc.u));
    return ud.f;
}

// ---------------- scratch ----------------
__device__ float g_attn[Bb*Ll*Nn];   // tokenizer logits -> softmax, [b][l][n]
__device__ float g_T[BLC];           // tokens [b][l][c]
__device__ float g_Tp[4*BLC];        // (a) T partials (b) GEMM split-K partials
__device__ float g_kq[BLC];          // [token][0:512]=k, [512:1024]=q
__device__ float g_Td[BLC];          // T_dash
__device__ float g_h[BLC];           // relu(f1)
__device__ float g_TK[BLC];          // T_out @ k_W + k_b
__device__ float g_U[BLC];           // TK @ q_W^T
__device__ float g_cb[Bb*Ll];        // q_b . TK[b,l]
__device__ float g_Wkq[Cc*Cc];       // [key_W | query_W]
__device__ float g_bkq[Cc];          // [key_b | query_b]

// =================================================================
// pack key/query weights into one [1024][1024] matrix + bias
// grid 1024 x 256, float4 per thread
// =================================================================
__global__ __launch_bounds__(256) void k_pack_kq(
    const float* __restrict__ kW, const float* __restrict__ kb,
    const float* __restrict__ qW, const float* __restrict__ qb,
    float* __restrict__ W, float* __restrict__ bias)
{
    int idx = blockIdx.x*256 + threadIdx.x;      // float4 over 1M floats
    int row = idx >> 8, c4 = idx & 255;
    float4 v;
    if (c4 < 128) v = ((const float4*)(kW + (size_t)row*Hh))[c4];
    else          v = ((const float4*)(qW + (size_t)row*Hh))[c4 - 128];
    ((float4*)(W + (size_t)row*Cc))[c4] = v;
    if (idx < 256) {
        float4 bv;
        if (idx < 128) bv = ((const float4*)kb)[idx];
        else           bv = ((const float4*)qb)[idx - 128];
        ((float4*)bias)[idx] = bv;
    }
}

// =================================================================
// K1: proj[b][l][n] = sum_c X[b,n,c]*tok_W[c,l] + tok_b[l]  (transposed out)
// grid 256 x 128; thread tile 4 pixels x 4 l (2 packed pairs)
// =================================================================
__global__ __launch_bounds__(128) void k1_proj(
    const float* __restrict__ X, const float* __restrict__ W,
    const float* __restrict__ bias, float* __restrict__ out)
{
    __shared__ float Xs[32][132];
    __shared__ float Ws[32][16];
    __shared__ float bs[16];

    int tid = threadIdx.x;
    int r0  = blockIdx.x * 128;
    int b   = r0 >> 10;
    int n0  = r0 & 1023;
    int lg  = tid & 3;
    int pg  = tid >> 2;

    if (tid < 16) bs[tid] = bias[tid];

    float2 acc[4][2];
#pragma unroll
    for (int i = 0; i < 4; i++) { acc[i][0] = make_float2(0.f,0.f); acc[i][1] = make_float2(0.f,0.f); }

    for (int k0 = 0; k0 < Cc; k0 += 32) {
        __syncthreads();
#pragma unroll
        for (int j = 0; j < 8; j++) {
            int v = tid + 128*j;
            int p = v >> 3, kq = v & 7;
            float4 f = *(const float4*)(X + (size_t)(r0 + p)*Cc + k0 + kq*4);
            Xs[kq*4+0][p] = f.x; Xs[kq*4+1][p] = f.y;
            Xs[kq*4+2][p] = f.z; Xs[kq*4+3][p] = f.w;
        }
        {
            int c = tid >> 2, lq = tid & 3;
            float4 wf = *(const float4*)(W + (size_t)(k0 + c)*Ll + lq*4);
            *(float4*)&Ws[c][lq*4] = wf;
        }
        __syncthreads();
#pragma unroll 8
        for (int kk = 0; kk < 32; kk++) {
            float4 xv = *(float4*)&Xs[kk][pg*4];
            float4 wv = *(float4*)&Ws[kk][lg*4];
            float2 w01 = make_float2(wv.x, wv.y), w23 = make_float2(wv.z, wv.w);
            float xr[4] = {xv.x, xv.y, xv.z, xv.w};
#pragma unroll
            for (int i = 0; i < 4; i++) {
                float2 ai = make_float2(xr[i], xr[i]);
                acc[i][0] = ffma2(ai, w01, acc[i][0]);
                acc[i][1] = ffma2(ai, w23, acc[i][1]);
            }
        }
    }
#pragma unroll
    for (int i = 0; i < 4; i++) {
        int n = n0 + pg*4 + i;
        float o[4] = {acc[i][0].x, acc[i][0].y, acc[i][1].x, acc[i][1].y};
#pragma unroll
        for (int j = 0; j < 4; j++) {
            int l = lg*4 + j;
            out[((b*Ll + l) << 10) + n] = o[j] + bs[l];
        }
    }
}

// =================================================================
// K2: softmax over n (1024) per [b][l] row. grid 512 x 256.
// =================================================================
__global__ __launch_bounds__(256) void k2_softmax(float* __restrict__ a)
{
    __shared__ float red[256];
    int row = blockIdx.x, tid = threadIdx.x;
    float4* p = (float4*)(a + ((size_t)row << 10));
    float4 v = p[tid];

    float m = fmaxf(fmaxf(v.x, v.y), fmaxf(v.z, v.w));
    red[tid] = m; __syncthreads();
    for (int s = 128; s > 0; s >>= 1) {
        if (tid < s) red[tid] = fmaxf(red[tid], red[tid+s]);
        __syncthreads();
    }
    float mx = red[0]; __syncthreads();

    v.x = __expf(v.x - mx); v.y = __expf(v.y - mx);
    v.z = __expf(v.z - mx); v.w = __expf(v.w - mx);
    red[tid] = v.x + v.y + v.z + v.w; __syncthreads();
    for (int s = 128; s > 0; s >>= 1) {
        if (tid < s) red[tid] += red[tid+s];
        __syncthreads();
    }
    float inv = 1.0f / red[0];
    v.x *= inv; v.y *= inv; v.z *= inv; v.w *= inv;
    p[tid] = v;
}

// =================================================================
// K3: partial T over 4 n-chunks (deterministic). packed FMA inner loop.
// grid (2 c-chunks, 4 n-chunks, 32 b) x 128.
// =================================================================
__global__ __launch_bounds__(128) void k3_aggregate(
    const float* __restrict__ X, const float* __restrict__ attn,
    float* __restrict__ Tp)
{
    __shared__ float As[256][16];
    int tid = threadIdx.x;
    int cx = blockIdx.x, ny = blockIdx.y, b = blockIdx.z;
    int n0 = ny * 256;

#pragma unroll
    for (int s = 0; s < 32; s++) {
        int v = tid + 128*s;
        int l = v >> 8, nn = v & 255;
        As[nn][l] = attn[((b*Ll + l) << 10) + n0 + nn];
    }
    __syncthreads();

    int c4 = cx*512 + tid*4;
    float2 acc[16][2];
#pragma unroll
    for (int l = 0; l < 16; l++) { acc[l][0] = make_float2(0.f,0.f); acc[l][1] = make_float2(0.f,0.f); }

    const float* Xb = X + (size_t)(b*Nn + n0)*Cc + c4;
#pragma unroll 4
    for (int nn = 0; nn < 256; nn++) {
        float4 xv = *(const float4*)(Xb + (size_t)nn*Cc);
        float2 x01 = make_float2(xv.x, xv.y), x23 = make_float2(xv.z, xv.w);
#pragma unroll
        for (int lq = 0; lq < 4; lq++) {
            float4 av = *(float4*)&As[nn][lq*4];
            float ar[4] = {av.x, av.y, av.z, av.w};
#pragma unroll
            for (int i = 0; i < 4; i++) {
                float2 a2 = make_float2(ar[i], ar[i]);
                int l = lq*4 + i;
                acc[l][0] = ffma2(a2, x01, acc[l][0]);
                acc[l][1] = ffma2(a2, x23, acc[l][1]);
            }
        }
    }
#pragma unroll
    for (int l = 0; l < 16; l++) {
        float4 o = make_float4(acc[l][0].x, acc[l][0].y, acc[l][1].x, acc[l][1].y);
        *(float4*)(Tp + (size_t)ny*BLC + ((b*Ll + l) << 10) + c4) = o;
    }
}

// K3b: T = sum of 4 partials. grid 512 x 256.
__global__ __launch_bounds__(256) void k3b_reduce(const float* __restrict__ Tp,
                                                  float* __restrict__ T)
{
    int idx = blockIdx.x*256 + threadIdx.x;
    const float4* p = (const float4*)Tp;
    float4 a = p[idx], b = p[idx + 131072], c = p[idx + 2*131072], d = p[idx + 3*131072];
    float4 o; o.x = a.x+b.x+c.x+d.x; o.y = a.y+b.y+c.y+d.y;
    o.z = a.z+b.z+c.z+d.z; o.w = a.w+b.w+c.w+d.w;
    ((float4*)T)[idx] = o;
}

// =================================================================
// Chain GEMM, fixed M=512, N=1024, K=1024, split-K=4 (slices of 256).
// P[s][m][n] partials. Tiles BM=32, BN=64, BK=16; 64 thr; tile 4x8 (packed).
// grid dim3(16, 16, 4)
// =================================================================
__global__ __launch_bounds__(64) void gemm_sk(
    const float* __restrict__ A, const float* __restrict__ Bm,
    float* __restrict__ P, int transB)
{
    __shared__ float As[16][36];
    __shared__ float Bs[16][68];
    int tid = threadIdx.x;
    int n0 = blockIdx.x * 64, m0 = blockIdx.y * 32, s = blockIdx.z;
    int kbeg = s * 256;
    int tm = tid & 7, tn = tid >> 3;

    float2 acc[4][4];
#pragma unroll
    for (int i = 0; i < 4; i++)
#pragma unroll
        for (int j = 0; j < 4; j++) acc[i][j] = make_float2(0.f, 0.f);

    for (int k0 = kbeg; k0 < kbeg + 256; k0 += 16) {
        __syncthreads();
#pragma unroll
        for (int j = 0; j < 2; j++) {
            int v = tid + 64*j;
            int m = v >> 2, kq = v & 3;
            float4 f = *(const float4*)(A + (size_t)(m0 + m)*Cc + k0 + kq*4);
            As[kq*4+0][m] = f.x; As[kq*4+1][m] = f.y;
            As[kq*4+2][m] = f.z; As[kq*4+3][m] = f.w;
        }
        if (!transB) {
#pragma unroll
            for (int j = 0; j < 4; j++) {
                int v = tid + 64*j;
                int k = v >> 4, nq = v & 15;
                float4 f = *(const float4*)(Bm + (size_t)(k0 + k)*Cc + n0 + nq*4);
                *(float4*)&Bs[k][nq*4] = f;
            }
        } else {
#pragma unroll
            for (int j = 0; j < 4; j++) {
                int v = tid + 64*j;
                int n = v >> 2, kq = v & 3;
                float4 f = *(const float4*)(Bm + (size_t)(n0 + n)*Cc + k0 + kq*4);
                Bs[kq*4+0][n] = f.x; Bs[kq*4+1][n] = f.y;
                Bs[kq*4+2][n] = f.z; Bs[kq*4+3][n] = f.w;
            }
        }
        __syncthreads();
#pragma unroll 8
        for (int kk = 0; kk < 16; kk++) {
            float4 a4 = *(float4*)&As[kk][tm*4];
            float4 b0 = *(float4*)&Bs[kk][tn*8];
            float4 b1 = *(float4*)&Bs[kk][tn*8 + 4];
            float ar[4] = {a4.x, a4.y, a4.z, a4.w};
            float2 bp[4] = { make_float2(b0.x,b0.y), make_float2(b0.z,b0.w),
                             make_float2(b1.x,b1.y), make_float2(b1.z,b1.w) };
#pragma unroll
            for (int i = 0; i < 4; i++) {
                float2 ai = make_float2(ar[i], ar[i]);
#pragma unroll
                for (int j = 0; j < 4; j++)
                    acc[i][j] = ffma2(ai, bp[j], acc[i][j]);
            }
        }
    }

    float* Pp = P + (size_t)s*MN;
#pragma unroll
    for (int i = 0; i < 4; i++) {
        int m = m0 + tm*4 + i;
        float* cp = Pp + (size_t)m*Cc + n0 + tn*8;
        *(float4*)cp       = make_float4(acc[i][0].x, acc[i][0].y, acc[i][1].x, acc[i][1].y);
        *(float4*)(cp + 4) = make_float4(acc[i][2].x, acc[i][2].y, acc[i][3].x, acc[i][3].y);
    }
}

// =================================================================
// GEMM epilogue: out = [res +] (relu)(sum_s P[s] + bias). grid 512 x 256.
// =================================================================
__global__ __launch_bounds__(256) void gemm_fin(
    const float* __restrict__ P, const float* __restrict__ bias,
    const float* __restrict__ Res, float* __restrict__ out, int doRelu)
{
    int idx = blockIdx.x*256 + threadIdx.x;   // float4 over 512K floats
    const float4* p = (const float4*)P;
    float4 a = p[idx], b = p[idx + 131072], c = p[idx + 2*131072], d = p[idx + 3*131072];
    float4 v; v.x = a.x+b.x+c.x+d.x; v.y = a.y+b.y+c.y+d.y;
    v.z = a.z+b.z+c.z+d.z; v.w = a.w+b.w+c.w+d.w;
    if (bias) {
        float4 bv = ((const float4*)bias)[idx & 255];
        v.x += bv.x; v.y += bv.y; v.z += bv.z; v.w += bv.w;
    }
    if (doRelu) {
        v.x = fmaxf(v.x, 0.f); v.y = fmaxf(v.y, 0.f);
        v.z = fmaxf(v.z, 0.f); v.w = fmaxf(v.w, 0.f);
    }
    if (Res) {
        float4 r = ((const float4*)Res)[idx];
        v.x += r.x; v.y += r.y; v.z += r.z; v.w += r.w;
    }
    ((float4*)out)[idx] = v;
}

// =================================================================
// K5: per-batch token self-attention (k|q packed in kq rows).
// =================================================================
__global__ __launch_bounds__(256) void k5_attn(
    const float* __restrict__ kq, const float* __restrict__ T,
    float* __restrict__ Td)
{
    __shared__ float sc[16][16];
    __shared__ float aw[16][16];
    int b = blockIdx.x, tid = threadIdx.x;
    int i = tid >> 4, j = tid & 15;

    const float4* kr = (const float4*)(kq + (size_t)(b*Ll + i)*Cc);
    const float4* qr = (const float4*)(kq + (size_t)(b*Ll + j)*Cc + Hh);
    float s = 0.f;
#pragma unroll 8
    for (int t = 0; t < 128; t++) {
        float4 kv = kr[t], qv = qr[t];
        s += kv.x*qv.x + kv.y*qv.y + kv.z*qv.z + kv.w*qv.w;
    }
    sc[i][j] = s;
    __syncthreads();

    if (tid < 16) {
        float m = -1e30f;
#pragma unroll
        for (int jj = 0; jj < 16; jj++) m = fmaxf(m, sc[tid][jj]);
        float sum = 0.f;
        float e[16];
#pragma unroll
        for (int jj = 0; jj < 16; jj++) { e[jj] = __expf(sc[tid][jj] - m); sum += e[jj]; }
        float inv = 1.f/sum;
#pragma unroll
        for (int jj = 0; jj < 16; jj++) aw[tid][jj] = e[jj]*inv;
    }
    __syncthreads();

    const float4* Tb = (const float4*)(T + (size_t)b*Ll*Cc);
    float4* Tdb = (float4*)(Td + (size_t)b*Ll*Cc);
#pragma unroll
    for (int t = 0; t < 16; t++) {
        int v = tid + 256*t;
        int ii = v >> 8, c4 = v & 255;
        float4 o = Tb[(ii << 8) + c4];
#pragma unroll
        for (int jj = 0; jj < 16; jj++) {
            float a = aw[ii][jj];
            float4 tv = Tb[(jj << 8) + c4];
            o.x += a*tv.x; o.y += a*tv.y; o.z += a*tv.z; o.w += a*tv.w;
        }
        Tdb[(ii << 8) + c4] = o;
    }
}

// =================================================================
// K9b: cb[r] = q_b . TK[r,:]
// =================================================================
__global__ __launch_bounds__(256) void k9b_cb(
    const float* __restrict__ TK, const float* __restrict__ qb,
    float* __restrict__ cb)
{
    int w = threadIdx.x >> 5, lane = threadIdx.x & 31;
    int row = blockIdx.x*8 + w;
    const float4* r4 = (const float4*)(TK + ((size_t)row << 10));
    const float4* b4 = (const float4*)qb;
    float s = 0.f;
#pragma unroll
    for (int j = 0; j < 8; j++) {
        int idx = lane + 32*j;
        float4 a = r4[idx], bb = b4[idx];
        s += a.x*bb.x + a.y*bb.y + a.z*bb.z + a.w*bb.w;
    }
#pragma unroll
    for (int off = 16; off > 0; off >>= 1)
        s += __shfl_xor_sync(0xFFFFFFFFu, s, off);
    if (lane == 0) cb[row] = s;
}

// =================================================================
// K10: projector pixel pass (packed FMA).
// =================================================================
__global__ __launch_bounds__(256) void k10_pixels(
    const float* __restrict__ X, const float* __restrict__ U,
    const float* __restrict__ Tout, const float* __restrict__ cb,
    float* __restrict__ Xout)
{
    extern __shared__ float sm[];
    float* Us = sm;
    float* Ts = sm + 16384;
    float* cbs = sm + 32768;

    int b  = blockIdx.x >> 4;
    int pb = blockIdx.x & 15;
    int tid = threadIdx.x;

    {
        const float4* u4 = (const float4*)(U + (size_t)b*16384);
        const float4* t4 = (const float4*)(Tout + (size_t)b*16384);
        float4* us4 = (float4*)Us; float4* ts4 = (float4*)Ts;
#pragma unroll
        for (int j = 0; j < 16; j++) {
            int idx = tid + 256*j;
            us4[idx] = u4[idx];
            ts4[idx] = t4[idx];
        }
        if (tid < 16) cbs[tid] = cb[b*Ll + tid];
    }
    __syncthreads();

    int w = tid >> 5, lane = tid & 31;
    for (int it = 0; it < 2; it++) {
        int p0 = pb*64 + it*32 + w*4;
        const float4* Xp = (const float4*)(X + (size_t)(b*Nn + p0)*Cc);
        float2 acc2[4][16];
#pragma unroll
        for (int p = 0; p < 4; p++)
#pragma unroll
            for (int l = 0; l < 16; l++) acc2[p][l] = make_float2(0.f, 0.f);

#pragma unroll
        for (int j = 0; j < 8; j++) {
            int c4 = lane + 32*j;
            float2 x01[4], x23[4];
#pragma unroll
            for (int p = 0; p < 4; p++) {
                float4 xv = Xp[(p << 8) + c4];
                x01[p] = make_float2(xv.x, xv.y);
                x23[p] = make_float2(xv.z, xv.w);
            }
#pragma unroll
            for (int l = 0; l < 16; l++) {
                float4 uv = ((float4*)(Us + (l << 10)))[c4];
                float2 u01 = make_float2(uv.x, uv.y), u23 = make_float2(uv.z, uv.w);
#pragma unroll
                for (int p = 0; p < 4; p++) {
                    acc2[p][l] = ffma2(x01[p], u01, acc2[p][l]);
                    acc2[p][l] = ffma2(x23[p], u23, acc2[p][l]);
                }
            }
        }
        float acc[4][16];
#pragma unroll
        for (int p = 0; p < 4; p++)
#pragma unroll
            for (int l = 0; l < 16; l++) acc[p][l] = acc2[p][l].x + acc2[p][l].y;

#pragma unroll
        for (int off = 16; off > 0; off >>= 1)
#pragma unroll
            for (int p = 0; p < 4; p++)
#pragma unroll
                for (int l = 0; l < 16; l++)
                    acc[p][l] += __shfl_xor_sync(0xFFFFFFFFu, acc[p][l], off);

#pragma unroll
        for (int p = 0; p < 4; p++) {
            float m = -1e30f;
#pragma unroll
            for (int l = 0; l < 16; l++) {
                acc[p][l] += cbs[l];
                m = fmaxf(m, acc[p][l]);
            }
            float s = 0.f;
#pragma unroll
            for (int l = 0; l < 16; l++) { acc[p][l] = __expf(acc[p][l] - m); s += acc[p][l]; }
            float inv = 1.f/s;
#pragma unroll
            for (int l = 0; l < 16; l++) acc[p][l] *= inv;
        }

        float4* Op = (float4*)(Xout + (size_t)(b*Nn + p0)*Cc);
#pragma unroll
        for (int j = 0; j < 8; j++) {
            int c4 = lane + 32*j;
            float2 o01[4], o23[4];
#pragma unroll
            for (int p = 0; p < 4; p++) {
                float4 xv = Xp[(p << 8) + c4];
                o01[p] = make_float2(xv.x, xv.y);
                o23[p] = make_float2(xv.z, xv.w);
            }
#pragma unroll
            for (int l = 0; l < 16; l++) {
                float4 tv = ((float4*)(Ts + (l << 10)))[c4];
                float2 t01 = make_float2(tv.x, tv.y), t23 = make_float2(tv.z, tv.w);
#pragma unroll
                for (int p = 0; p < 4; p++) {
                    float2 a2 = make_float2(acc[p][l], acc[p][l]);
                    o01[p] = ffma2(a2, t01, o01[p]);
                    o23[p] = ffma2(a2, t23, o23[p]);
                }
            }
#pragma unroll
            for (int p = 0; p < 4; p++)
                Op[(p << 8) + c4] = make_float4(o01[p].x, o01[p].y, o23[p].x, o23[p].y);
        }
    }
}

// =================================================================
extern "C" void kernel_launch(void* const* d_in, const int* in_sizes, int n_in,
                              void* d_out, int out_size)
{
    const float* X       = (const float*)d_in[0];
    const float* tok_W   = (const float*)d_in[2];
    const float* tok_b   = (const float*)d_in[3];
    const float* key_W   = (const float*)d_in[4];
    const float* key_b   = (const float*)d_in[5];
    const float* query_W = (const float*)d_in[6];
    const float* query_b = (const float*)d_in[7];
    const float* f1_W    = (const float*)d_in[8];
    const float* f1_b    = (const float*)d_in[9];
    const float* f2_W    = (const float*)d_in[10];
    const float* f2_b    = (const float*)d_in[11];
    const float* q_W     = (const float*)d_in[12];
    const float* q_b     = (const float*)d_in[13];
    const float* k_W     = (const float*)d_in[14];
    const float* k_b     = (const float*)d_in[15];

    float* Xout = (float*)d_out;
    float* Tout = (float*)d_out + (size_t)BNC;

    float *p_attn, *p_T, *p_Tp, *p_kq, *p_Td, *p_h, *p_TK, *p_U, *p_cb, *p_Wkq, *p_bkq;
    cudaGetSymbolAddress((void**)&p_attn, g_attn);
    cudaGetSymbolAddress((void**)&p_T,    g_T);
    cudaGetSymbolAddress((void**)&p_Tp,   g_Tp);
    cudaGetSymbolAddress((void**)&p_kq,   g_kq);
    cudaGetSymbolAddress((void**)&p_Td,   g_Td);
    cudaGetSymbolAddress((void**)&p_h,    g_h);
    cudaGetSymbolAddress((void**)&p_TK,   g_TK);
    cudaGetSymbolAddress((void**)&p_U,    g_U);
    cudaGetSymbolAddress((void**)&p_cb,   g_cb);
    cudaGetSymbolAddress((void**)&p_Wkq,  g_Wkq);
    cudaGetSymbolAddress((void**)&p_bkq,  g_bkq);

    cudaFuncSetAttribute(k10_pixels,
        cudaFuncAttributeMaxDynamicSharedMemorySize, (32768 + 16) * 4);

    // Phase A: tokenizer (pack_kq overlaps nothing but is independent)
    k_pack_kq<<<1024, 256>>>(key_W, key_b, query_W, query_b, p_Wkq, p_bkq);
    k1_proj<<<256, 128>>>(X, tok_W, tok_b, p_attn);
    k2_softmax<<<512, 256>>>(p_attn);
    k3_aggregate<<<dim3(2, 4, 32), 128>>>(X, p_attn, p_Tp);
    k3b_reduce<<<512, 256>>>(p_Tp, p_T);

    // Phase B: token transformer (split-K GEMMs + epilogues)
    gemm_sk<<<dim3(16, 16, 4), 64>>>(p_T, p_Wkq, p_Tp, 0);
    gemm_fin<<<512, 256>>>(p_Tp, p_bkq, nullptr, p_kq, 0);
    k5_attn<<<32, 256>>>(p_kq, p_T, p_Td);
    gemm_sk<<<dim3(16, 16, 4), 64>>>(p_Td, f1_W, p_Tp, 0);
    gemm_fin<<<512, 256>>>(p_Tp, f1_b, nullptr, p_h, 1);
    gemm_sk<<<dim3(16, 16, 4), 64>>>(p_h, f2_W, p_Tp, 0);
    gemm_fin<<<512, 256>>>(p_Tp, f2_b, p_Td, Tout, 0);

    // Projector token-side transforms
    gemm_sk<<<dim3(16, 16, 4), 64>>>(Tout, k_W, p_Tp, 0);
    gemm_fin<<<512, 256>>>(p_Tp, k_b, nullptr, p_TK, 0);
    gemm_sk<<<dim3(16, 16, 4), 64>>>(p_TK, q_W, p_Tp, 1);
    gemm_fin<<<512, 256>>>(p_Tp, nullptr, nullptr, p_U, 0);
    k9b_cb<<<64, 256>>>(p_TK, q_b, p_cb);

    // Phase C: pixel pass
    k10_pixels<<<512, 256, (32768 + 16) * 4>>>(X, p_U, Tout, p_cb, Xout);

    (void)in_sizes; (void)n_in; (void)out_size;
}